// round 3
// baseline (speedup 1.0000x reference)
#include <cuda_runtime.h>

// ADC module: out = x + alpha_c * sum_{3x3, zero-pad} |x - neighbor|
// x: (8, 64, 256, 256) fp32, alpha: (64,) fp32 (shape (1,64,1,1))
//
// Strategy: one warp per 32-row strip of one (b,c) image.
// Each lane owns 8 consecutive columns (2x float4), full 256-wide row per warp.
// Roll 3 rows (prev/cur/next) through registers; lane-edge halos via shfl;
// image-edge halos are zero (pad). 1 read + 1 write per element of DRAM traffic.

#define IMG_H 256
#define IMG_W 256
#define STRIP_ROWS 32
#define N_IMG (8 * 64)
#define STRIPS_PER_IMG (IMG_H / STRIP_ROWS)   // 8
#define TOTAL_WARPS (N_IMG * STRIPS_PER_IMG)  // 4096
#define BLOCK_THREADS 128
#define GRID_BLOCKS (TOTAL_WARPS * 32 / BLOCK_THREADS)  // 1024

struct Row {
    float v[8];
    float lh;   // value at col (lane*8 - 1), 0 at image edge
    float rh;   // value at col (lane*8 + 8), 0 at image edge
};

__device__ __forceinline__ Row load_row(const float* __restrict__ img, int r, int lane) {
    Row row;
    if (r >= 0 && r < IMG_H) {
        const float4* p = reinterpret_cast<const float4*>(img + (size_t)r * IMG_W + lane * 8);
        float4 a = __ldg(p);
        float4 b = __ldg(p + 1);
        row.v[0] = a.x; row.v[1] = a.y; row.v[2] = a.z; row.v[3] = a.w;
        row.v[4] = b.x; row.v[5] = b.y; row.v[6] = b.z; row.v[7] = b.w;
    } else {
#pragma unroll
        for (int i = 0; i < 8; i++) row.v[i] = 0.0f;
    }
    // r is warp-uniform -> no divergence; all lanes participate in shfl.
    float left  = __shfl_up_sync(0xffffffffu, row.v[7], 1);
    float right = __shfl_down_sync(0xffffffffu, row.v[0], 1);
    row.lh = (lane == 0)  ? 0.0f : left;
    row.rh = (lane == 31) ? 0.0f : right;
    return row;
}

__global__ void __launch_bounds__(BLOCK_THREADS)
adc_kernel(const float* __restrict__ x, const float* __restrict__ alpha,
           float* __restrict__ out) {
    int gwarp = (blockIdx.x * BLOCK_THREADS + threadIdx.x) >> 5;
    int lane  = threadIdx.x & 31;

    int img   = gwarp / STRIPS_PER_IMG;   // 0..511  (b*64 + c)
    int strip = gwarp - img * STRIPS_PER_IMG;
    int ch    = img & 63;                 // channel index
    float a   = __ldg(&alpha[ch]);

    const float* xi = x   + (size_t)img * IMG_H * IMG_W;
    float*       oi = out + (size_t)img * IMG_H * IMG_W;

    int r0 = strip * STRIP_ROWS;

    Row prev = load_row(xi, r0 - 1, lane);
    Row cur  = load_row(xi, r0,     lane);

#pragma unroll 4
    for (int r = r0; r < r0 + STRIP_ROWS; ++r) {
        Row next = load_row(xi, r + 1, lane);

        float o[8];
#pragma unroll
        for (int j = 0; j < 8; ++j) {
            float c  = cur.v[j];
            float l  = (j == 0) ? cur.lh  : cur.v[j - 1];
            float rr = (j == 7) ? cur.rh  : cur.v[j + 1];
            float pl = (j == 0) ? prev.lh : prev.v[j - 1];
            float pc = prev.v[j];
            float pr = (j == 7) ? prev.rh : prev.v[j + 1];
            float nl = (j == 0) ? next.lh : next.v[j - 1];
            float nc = next.v[j];
            float nr = (j == 7) ? next.rh : next.v[j + 1];

            // center tap |c - c| == 0 for finite inputs -> skipped
            float s = fabsf(c - pl) + fabsf(c - pc) + fabsf(c - pr)
                    + fabsf(c - l)                   + fabsf(c - rr)
                    + fabsf(c - nl) + fabsf(c - nc) + fabsf(c - nr);
            o[j] = fmaf(a, s, c);
        }

        float4* po = reinterpret_cast<float4*>(oi + (size_t)r * IMG_W + lane * 8);
        po[0] = make_float4(o[0], o[1], o[2], o[3]);
        po[1] = make_float4(o[4], o[5], o[6], o[7]);

        prev = cur;
        cur  = next;
    }
}

extern "C" void kernel_launch(void* const* d_in, const int* in_sizes, int n_in,
                              void* d_out, int out_size) {
    const float* x     = (const float*)d_in[0];
    const float* alpha = (const float*)d_in[1];
    float*       out   = (float*)d_out;
    adc_kernel<<<GRID_BLOCKS, BLOCK_THREADS>>>(x, alpha, out);
}